// round 3
// baseline (speedup 1.0000x reference)
#include <cuda_runtime.h>

#define NS 32
#define NI 8
#define NO 8
#define NT 4096
#define NB 256
#define NCH 128
#define CS 32
#define NSUB 256
#define SS 16
#define NAUGA 72   // [x(32); u0..u4(40)]
#define NAUGC 48   // [x(32); u0(8); u1(8)]
#define TPC 64

// ---- persistent device scratch (module globals; no runtime allocation) ----
__device__ float g_GTA[NAUGA*NS];   // [M4 | H0..H4]^T  (col j holds row of length 32)
__device__ float g_GTC[NAUGC*NS];   // [M  | F0 | F1]^T
__device__ float g_M16T[NS*NS];
__device__ float g_M32T[NS*NS];
__device__ float g_p[NB*NCH*2*NS];     // zero-start partials @ local steps 16,32
__device__ float g_xstart[NB*NSUB*NS]; // 16-step subchunk start states

// ---- Dopri5 tableau in constant memory (no per-thread arrays anywhere) ----
__constant__ float c_ac[6][5] = {
    {0.f,0.f,0.f,0.f,0.f},
    {0.2f,0.f,0.f,0.f,0.f},
    {(float)(3.0/40.0),(float)(9.0/40.0),0.f,0.f,0.f},
    {(float)(44.0/45.0),(float)(-56.0/15.0),(float)(32.0/9.0),0.f,0.f},
    {(float)(19372.0/6561.0),(float)(-25360.0/2187.0),(float)(64448.0/6561.0),(float)(-212.0/729.0),0.f},
    {(float)(9017.0/3168.0),(float)(-355.0/33.0),(float)(46732.0/5247.0),(float)(49.0/176.0),(float)(-5103.0/18656.0)}
};
__constant__ float c_cs[6] = {0.f, 0.2f, 0.3f, 0.8f, (float)(8.0/9.0), 1.f};
__constant__ float c_bb[6] = {(float)(35.0/384.0), 0.f, (float)(500.0/1113.0),
                              (float)(125.0/192.0), (float)(-2187.0/6784.0), (float)(11.0/84.0)};

// ============================================================
// Setup: exact affine map of one Dopri5 step, powers, transposes.
// 1024 threads: (i = row, j = col). Scalar per-thread state only.
// ============================================================
__global__ void __launch_bounds__(1024) setup_kernel(const float* __restrict__ t,
                                                     const float* __restrict__ Am,
                                                     const float* __restrict__ Bm) {
    __shared__ float sA[NS*NS];      // A, later M
    __shared__ float sB[NS*NI];
    __shared__ float sP[6][NS*NS];
    __shared__ float sQ[6][NS*NI];
    __shared__ float sR[6][NS*NI];
    __shared__ float sT[NS*NS];      // staging / M2
    __shared__ float sX[2*NS*NI];    // F0 | F1

    const int tid = threadIdx.x;
    const int i = tid >> 5, j = tid & 31;
    const float dt = t[1] - t[0];

    sA[tid] = Am[tid];
    if (j < NI) sB[i*NI + j] = Bm[i*NI + j];
    __syncthreads();

    // Stage recurrences: P_s = A(I + dt Σ a_sj P_j); Q_s = A(dt Σ a_sj Q_j)+B; R_s = A(dt Σ a_sj R_j)+c_s B
    for (int s = 0; s < 6; s++) {
        float tv = (i == j) ? 1.f : 0.f;
        float qv = 0.f, rv = 0.f;
        for (int js = 0; js < s; js++) {
            float a = dt * c_ac[s][js];
            tv += a * sP[js][tid];
            if (j < NI) {
                qv += a * sQ[js][i*NI + j];
                rv += a * sR[js][i*NI + j];
            }
        }
        __syncthreads();
        sT[tid] = tv;
        if (j < NI) { sX[i*NI + j] = qv; sX[NS*NI + i*NI + j] = rv; }
        __syncthreads();
        float pv = 0.f;
#pragma unroll
        for (int k = 0; k < NS; k++) pv += sA[i*NS + k] * sT[k*NS + j];
        sP[s][tid] = pv;
        if (j < NI) {
            float qa = 0.f, ra = 0.f;
#pragma unroll
            for (int k = 0; k < NS; k++) {
                qa += sA[i*NS + k] * sX[k*NI + j];
                ra += sA[i*NS + k] * sX[NS*NI + k*NI + j];
            }
            sQ[s][i*NI + j] = qa + sB[i*NI + j];
            sR[s][i*NI + j] = ra + c_cs[s] * sB[i*NI + j];
        }
        __syncthreads();
    }

    // M = I + dt Σ b_s P_s;  F0 = G0 - Gd, F1 = Gd
    float mv = (i == j) ? 1.f : 0.f;
    for (int s = 0; s < 6; s++) mv += dt * c_bb[s] * sP[s][tid];
    float f0v = 0.f, f1v = 0.f;
    if (j < NI) {
        float g0 = 0.f, gd = 0.f;
        for (int s = 0; s < 6; s++) {
            g0 += dt * c_bb[s] * sQ[s][i*NI + j];
            gd += dt * c_bb[s] * sR[s][i*NI + j];
        }
        f0v = g0 - gd; f1v = gd;
    }
    __syncthreads();
    sA[tid] = mv;                       // sA = M
    g_GTC[j*NS + i] = mv;               // M^T into GTC cols 0..31
    if (j < NI) {
        sX[i*NI + j] = f0v; sX[NS*NI + i*NI + j] = f1v;
        g_GTC[(NS + j)*NS + i] = f0v;   // F0^T -> cols 32..39
        g_GTC[(NS + NI + j)*NS + i] = f1v; // F1^T -> cols 40..47
    }
    __syncthreads();

    // M2
    float m2 = 0.f;
#pragma unroll
    for (int k = 0; k < NS; k++) m2 += sA[i*NS + k] * sA[k*NS + j];
    __syncthreads();
    sT[tid] = m2;
    __syncthreads();
    // M3
    float m3 = 0.f;
#pragma unroll
    for (int k = 0; k < NS; k++) m3 += sT[i*NS + k] * sA[k*NS + j];
    sP[0][tid] = m3;
    __syncthreads();

    // Quad-step input maps: H0=M3F0, H1=M3F1+M2F0, H2=M2F1+MF0, H3=MF1+F0, H4=F1
    if (j < NI) {
        float h0 = 0.f, h1 = 0.f, h2 = 0.f, h3 = 0.f;
#pragma unroll
        for (int k = 0; k < NS; k++) {
            float fk0 = sX[k*NI + j], fk1 = sX[NS*NI + k*NI + j];
            h0 += sP[0][i*NS + k] * fk0;
            h1 += sP[0][i*NS + k] * fk1 + sT[i*NS + k] * fk0;
            h2 += sT[i*NS + k] * fk1 + sA[i*NS + k] * fk0;
            h3 += sA[i*NS + k] * fk1;
        }
        h3 += sX[i*NI + j];
        g_GTA[(NS + 0*NI + j)*NS + i] = h0;
        g_GTA[(NS + 1*NI + j)*NS + i] = h1;
        g_GTA[(NS + 2*NI + j)*NS + i] = h2;
        g_GTA[(NS + 3*NI + j)*NS + i] = h3;
        g_GTA[(NS + 4*NI + j)*NS + i] = sX[NS*NI + i*NI + j];
    }
    // M4
    float m4 = 0.f;
#pragma unroll
    for (int k = 0; k < NS; k++) m4 += sT[i*NS + k] * sT[k*NS + j];
    sP[1][tid] = m4;
    g_GTA[j*NS + i] = m4;               // M4^T into GTA cols 0..31
    __syncthreads();
    // M8
    float m8 = 0.f;
#pragma unroll
    for (int k = 0; k < NS; k++) m8 += sP[1][i*NS + k] * sP[1][k*NS + j];
    sP[2][tid] = m8;
    __syncthreads();
    // M16
    float m16 = 0.f;
#pragma unroll
    for (int k = 0; k < NS; k++) m16 += sP[2][i*NS + k] * sP[2][k*NS + j];
    sP[3][tid] = m16;
    g_M16T[j*NS + i] = m16;
    __syncthreads();
    // M32
    float m32 = 0.f;
#pragma unroll
    for (int k = 0; k < NS; k++) m32 += sP[3][i*NS + k] * sP[3][k*NS + j];
    g_M32T[j*NS + i] = m32;
}

// ============================================================
// Pass A: zero-start chunk partials, quad-step compressed.
// 32-thread blocks; thread = (batch lane, chunk). z in shared (thread-private
// columns, no barriers). Snapshots at local steps 16 and 32.
// ============================================================
__global__ void __launch_bounds__(32) passA_kernel(const float* __restrict__ u) {
    __shared__ float sG[NAUGA*NS];
    __shared__ float sz[NAUGA*32];
    const int lane = threadIdx.x;
    const int c = blockIdx.x >> 3;
    const int b = ((blockIdx.x & 7) << 5) + lane;

    for (int k = lane; k < NAUGA*NS; k += 32) sG[k] = g_GTA[k];
    // x = 0
#pragma unroll
    for (int ii = 0; ii < NS; ii++) sz[ii*32 + lane] = 0.f;

    const int n0 = c * CS;
    const int nq = (c == NCH - 1) ? 4 : 8;
    const float* __restrict__ ub = u + (size_t)b * NT * NI;
    // u0
    {
        float4 a0 = *(const float4*)&ub[n0*NI];
        float4 a1 = *(const float4*)&ub[n0*NI + 4];
        sz[(NS+0)*32+lane]=a0.x; sz[(NS+1)*32+lane]=a0.y;
        sz[(NS+2)*32+lane]=a0.z; sz[(NS+3)*32+lane]=a0.w;
        sz[(NS+4)*32+lane]=a1.x; sz[(NS+5)*32+lane]=a1.y;
        sz[(NS+6)*32+lane]=a1.z; sz[(NS+7)*32+lane]=a1.w;
    }
    __syncwarp();
    float* __restrict__ pout = &g_p[(size_t)(b*NCH + c) * 2 * NS];

#pragma unroll 1
    for (int q = 0; q < nq; q++) {
        const int n = n0 + q*4;
        float4 u4a, u4b;
#pragma unroll
        for (int p = 1; p <= 4; p++) {
            float4 a0 = *(const float4*)&ub[(n+p)*NI];
            float4 a1 = *(const float4*)&ub[(n+p)*NI + 4];
            const int base = NS + 8*p;
            sz[(base+0)*32+lane]=a0.x; sz[(base+1)*32+lane]=a0.y;
            sz[(base+2)*32+lane]=a0.z; sz[(base+3)*32+lane]=a0.w;
            sz[(base+4)*32+lane]=a1.x; sz[(base+5)*32+lane]=a1.y;
            sz[(base+6)*32+lane]=a1.z; sz[(base+7)*32+lane]=a1.w;
            if (p == 4) { u4a = a0; u4b = a1; }
        }
        float acc[NS];
#pragma unroll
        for (int ii = 0; ii < NS; ii++) acc[ii] = 0.f;
#pragma unroll 1
        for (int jj = 0; jj < NAUGA; jj++) {
            const float zj = sz[jj*32 + lane];
            const float4* g4 = (const float4*)&sG[jj*NS];
#pragma unroll
            for (int qq = 0; qq < 8; qq++) {
                float4 w = g4[qq];
                acc[4*qq+0] = fmaf(w.x, zj, acc[4*qq+0]);
                acc[4*qq+1] = fmaf(w.y, zj, acc[4*qq+1]);
                acc[4*qq+2] = fmaf(w.z, zj, acc[4*qq+2]);
                acc[4*qq+3] = fmaf(w.w, zj, acc[4*qq+3]);
            }
        }
        // x <- acc ; u0 <- u4
#pragma unroll
        for (int ii = 0; ii < NS; ii++) sz[ii*32 + lane] = acc[ii];
        sz[(NS+0)*32+lane]=u4a.x; sz[(NS+1)*32+lane]=u4a.y;
        sz[(NS+2)*32+lane]=u4a.z; sz[(NS+3)*32+lane]=u4a.w;
        sz[(NS+4)*32+lane]=u4b.x; sz[(NS+5)*32+lane]=u4b.y;
        sz[(NS+6)*32+lane]=u4b.z; sz[(NS+7)*32+lane]=u4b.w;
        if ((q & 3) == 3) {
            float4* po = (float4*)&pout[(q >> 2) * NS];
#pragma unroll
            for (int w2 = 0; w2 < 8; w2++)
                po[w2] = make_float4(acc[4*w2], acc[4*w2+1], acc[4*w2+2], acc[4*w2+3]);
        }
    }
}

// ============================================================
// Pass B: sequential chunk-boundary scan (warp per batch, shfl matvec, M^32)
// ============================================================
__global__ void __launch_bounds__(32) passB_kernel(const float* __restrict__ x0) {
    __shared__ float sMT[NS*NS];
    const int lane = threadIdx.x;
    const int b = blockIdx.x;
    for (int k = lane; k < NS*NS; k += 32) sMT[k] = g_M32T[k];
    __syncthreads();

    float x = x0[b*NS + lane];
    g_xstart[((size_t)b*NSUB + 0)*NS + lane] = x;
#pragma unroll 1
    for (int cc = 0; cc < NCH - 1; cc++) {
        float a0 = g_p[((size_t)(b*NCH + cc)*2 + 1)*NS + lane];
        float a1 = 0.f;
#pragma unroll
        for (int jv = 0; jv < NS; jv += 2) {
            a0 = fmaf(sMT[jv*NS + lane],     __shfl_sync(0xffffffffu, x, jv),   a0);
            a1 = fmaf(sMT[(jv+1)*NS + lane], __shfl_sync(0xffffffffu, x, jv+1), a1);
        }
        x = a0 + a1;
        g_xstart[((size_t)b*NSUB + 2*(cc+1))*NS + lane] = x;
    }
}

// ============================================================
// Pass B2: parallel midpoint refinement (warp per (batch,chunk), M^16)
// ============================================================
__global__ void __launch_bounds__(128) passB2_kernel() {
    __shared__ float s16[NS*NS];
    const int tid = threadIdx.x;
    const int lane = tid & 31, w = tid >> 5;
    const int gw = blockIdx.x * 4 + w;      // 0 .. NB*NCH-1
    const int b = gw >> 7;
    const int c = gw & (NCH-1);
    for (int k = tid; k < NS*NS; k += 128) s16[k] = g_M16T[k];
    __syncthreads();

    float x = g_xstart[((size_t)b*NSUB + 2*c)*NS + lane];
    float a0 = g_p[((size_t)(b*NCH + c)*2 + 0)*NS + lane];
    float a1 = 0.f;
#pragma unroll
    for (int jv = 0; jv < NS; jv += 2) {
        a0 = fmaf(s16[jv*NS + lane],     __shfl_sync(0xffffffffu, x, jv),   a0);
        a1 = fmaf(s16[(jv+1)*NS + lane], __shfl_sync(0xffffffffu, x, jv+1), a1);
    }
    g_xstart[((size_t)b*NSUB + 2*c + 1)*NS + lane] = a0 + a1;
}

// ============================================================
// Pass C: final trajectory + outputs. Thread = (batch, 16-step subchunk).
// z in shared thread-private columns; G^T = [M|F0|F1]^T in shared.
// ============================================================
__global__ void __launch_bounds__(TPC) passC_kernel(const float* __restrict__ u,
                                                    const float* __restrict__ Cm,
                                                    const float* __restrict__ Dm,
                                                    float* __restrict__ xs,
                                                    float* __restrict__ ys) {
    __shared__ float sG[NAUGC*NS];
    __shared__ float sC[NO*NS];
    __shared__ float sD[NO*NI];
    __shared__ float sz[NAUGC*TPC];
    const int tid = threadIdx.x;
    const int sc = blockIdx.x >> 2;
    const int b = ((blockIdx.x & 3) << 6) + tid;
    for (int k = tid; k < NAUGC*NS; k += TPC) sG[k] = g_GTC[k];
    for (int k = tid; k < NO*NS; k += TPC) sC[k] = Cm[k];
    if (tid < NO*NI) sD[tid] = Dm[tid];
    __syncthreads();

    const int n0 = sc * SS;
    const int nsteps = (sc == NSUB - 1) ? (SS - 1) : SS;
    const float* __restrict__ ubp = u + (size_t)b * NT * NI;
    float* __restrict__ xsb = xs + (size_t)b * NT * NS;
    float* __restrict__ ysb = ys + (size_t)b * NT * NO;

    // init z: x from g_xstart, u0 from u(n0)
    float4 u0a, u0b;
    {
        const float4* xst = (const float4*)&g_xstart[((size_t)b*NSUB + sc)*NS];
#pragma unroll
        for (int w2 = 0; w2 < 8; w2++) {
            float4 v = xst[w2];
            sz[(4*w2+0)*TPC+tid] = v.x; sz[(4*w2+1)*TPC+tid] = v.y;
            sz[(4*w2+2)*TPC+tid] = v.z; sz[(4*w2+3)*TPC+tid] = v.w;
        }
        u0a = *(const float4*)&ubp[n0*NI];
        u0b = *(const float4*)&ubp[n0*NI + 4];
        sz[(NS+0)*TPC+tid]=u0a.x; sz[(NS+1)*TPC+tid]=u0a.y;
        sz[(NS+2)*TPC+tid]=u0a.z; sz[(NS+3)*TPC+tid]=u0a.w;
        sz[(NS+4)*TPC+tid]=u0b.x; sz[(NS+5)*TPC+tid]=u0b.y;
        sz[(NS+6)*TPC+tid]=u0b.z; sz[(NS+7)*TPC+tid]=u0b.w;
    }
    __syncwarp();

    if (sc == 0) {
        // emit t=0 sample: x0 and y0 = C x0 + D u0
        float4* xo = (float4*)xsb;
#pragma unroll
        for (int w2 = 0; w2 < 8; w2++) {
            xo[w2] = make_float4(sz[(4*w2+0)*TPC+tid], sz[(4*w2+1)*TPC+tid],
                                 sz[(4*w2+2)*TPC+tid], sz[(4*w2+3)*TPC+tid]);
        }
        float y[NO];
#pragma unroll
        for (int o = 0; o < NO; o++) {
            float a = 0.f;
#pragma unroll
            for (int jv = 0; jv < NS; jv++) a = fmaf(sC[o*NS + jv], sz[jv*TPC+tid], a);
            a = fmaf(sD[o*NI+0],u0a.x,a); a = fmaf(sD[o*NI+1],u0a.y,a);
            a = fmaf(sD[o*NI+2],u0a.z,a); a = fmaf(sD[o*NI+3],u0a.w,a);
            a = fmaf(sD[o*NI+4],u0b.x,a); a = fmaf(sD[o*NI+5],u0b.y,a);
            a = fmaf(sD[o*NI+6],u0b.z,a); a = fmaf(sD[o*NI+7],u0b.w,a);
            y[o] = a;
        }
        ((float4*)ysb)[0] = make_float4(y[0], y[1], y[2], y[3]);
        ((float4*)ysb)[1] = make_float4(y[4], y[5], y[6], y[7]);
    }

#pragma unroll 1
    for (int s2 = 0; s2 < nsteps; s2++) {
        const int n = n0 + s2;
        float4 u1a = *(const float4*)&ubp[(n+1)*NI];
        float4 u1b = *(const float4*)&ubp[(n+1)*NI + 4];
        sz[(NS+NI+0)*TPC+tid]=u1a.x; sz[(NS+NI+1)*TPC+tid]=u1a.y;
        sz[(NS+NI+2)*TPC+tid]=u1a.z; sz[(NS+NI+3)*TPC+tid]=u1a.w;
        sz[(NS+NI+4)*TPC+tid]=u1b.x; sz[(NS+NI+5)*TPC+tid]=u1b.y;
        sz[(NS+NI+6)*TPC+tid]=u1b.z; sz[(NS+NI+7)*TPC+tid]=u1b.w;

        float acc[NS];
#pragma unroll
        for (int ii = 0; ii < NS; ii++) acc[ii] = 0.f;
#pragma unroll 1
        for (int jj = 0; jj < NAUGC; jj++) {
            const float zj = sz[jj*TPC + tid];
            const float4* g4 = (const float4*)&sG[jj*NS];
#pragma unroll
            for (int qq = 0; qq < 8; qq++) {
                float4 w = g4[qq];
                acc[4*qq+0] = fmaf(w.x, zj, acc[4*qq+0]);
                acc[4*qq+1] = fmaf(w.y, zj, acc[4*qq+1]);
                acc[4*qq+2] = fmaf(w.z, zj, acc[4*qq+2]);
                acc[4*qq+3] = fmaf(w.w, zj, acc[4*qq+3]);
            }
        }
        // z: x <- acc, u0 <- u1
#pragma unroll
        for (int ii = 0; ii < NS; ii++) sz[ii*TPC + tid] = acc[ii];
        sz[(NS+0)*TPC+tid]=u1a.x; sz[(NS+1)*TPC+tid]=u1a.y;
        sz[(NS+2)*TPC+tid]=u1a.z; sz[(NS+3)*TPC+tid]=u1a.w;
        sz[(NS+4)*TPC+tid]=u1b.x; sz[(NS+5)*TPC+tid]=u1b.y;
        sz[(NS+6)*TPC+tid]=u1b.z; sz[(NS+7)*TPC+tid]=u1b.w;

        float4* xo = (float4*)&xsb[(size_t)(n+1)*NS];
#pragma unroll
        for (int w2 = 0; w2 < 8; w2++)
            xo[w2] = make_float4(acc[4*w2], acc[4*w2+1], acc[4*w2+2], acc[4*w2+3]);

        float y[NO];
#pragma unroll
        for (int o = 0; o < NO; o++) {
            float a = 0.f;
#pragma unroll
            for (int jv = 0; jv < NS; jv++) a = fmaf(sC[o*NS + jv], acc[jv], a);
            a = fmaf(sD[o*NI+0],u1a.x,a); a = fmaf(sD[o*NI+1],u1a.y,a);
            a = fmaf(sD[o*NI+2],u1a.z,a); a = fmaf(sD[o*NI+3],u1a.w,a);
            a = fmaf(sD[o*NI+4],u1b.x,a); a = fmaf(sD[o*NI+5],u1b.y,a);
            a = fmaf(sD[o*NI+6],u1b.z,a); a = fmaf(sD[o*NI+7],u1b.w,a);
            y[o] = a;
        }
        float4* yo = (float4*)&ysb[(size_t)(n+1)*NO];
        yo[0] = make_float4(y[0], y[1], y[2], y[3]);
        yo[1] = make_float4(y[4], y[5], y[6], y[7]);
    }
}

// ============================================================
extern "C" void kernel_launch(void* const* d_in, const int* in_sizes, int n_in,
                              void* d_out, int out_size) {
    const float* t  = (const float*)d_in[0];
    const float* u  = (const float*)d_in[1];
    const float* x0 = (const float*)d_in[2];
    const float* A  = (const float*)d_in[3];
    const float* B  = (const float*)d_in[4];
    const float* C  = (const float*)d_in[5];
    const float* D  = (const float*)d_in[6];
    float* xs = (float*)d_out;
    float* ys = xs + (size_t)NB * NT * NS;

    setup_kernel<<<1, 1024>>>(t, A, B);
    passA_kernel<<<NCH * 8, 32>>>(u);
    passB_kernel<<<NB, 32>>>(x0);
    passB2_kernel<<<NB * NCH / 4, 128>>>();
    passC_kernel<<<NSUB * 4, TPC>>>(u, C, D, xs, ys);
}

// round 5
// speedup vs baseline: 1.5659x; 1.5659x over previous
#include <cuda_runtime.h>

#define NS 32
#define NI 8
#define NO 8
#define NT 4096
#define NB 256
#define NCH 128
#define CS 32
#define NSUB 256
#define SS 16
#define NAUGA 72   // [x(32); u0..u4(40)]
#define NAUGC 48   // [x(32); u0(8); u1(8)]
#define TPC 64

// ---- persistent device scratch (module globals; no runtime allocation) ----
__device__ float g_uT[(size_t)NT*NI*NB];          // u transposed: [n][k][b]
__device__ float g_GTA[NAUGA*NS];                 // [M4 | H0..H4]^T (scalar, passA)
__device__ __align__(16) float2 g_GTC2[NAUGC*NS]; // [M | F0 | F1]^T value-duplicated f32x2
__device__ float g_M16T[NS*NS];
__device__ float g_M32T[NS*NS];
__device__ float g_p[NB*NCH*2*NS];                // zero-start partials @ local steps 16,32
__device__ float g_xstart[NB*NSUB*NS];            // 16-step subchunk start states

// ---- Dopri5 tableau in constant memory ----
__constant__ float c_ac[6][5] = {
    {0.f,0.f,0.f,0.f,0.f},
    {0.2f,0.f,0.f,0.f,0.f},
    {(float)(3.0/40.0),(float)(9.0/40.0),0.f,0.f,0.f},
    {(float)(44.0/45.0),(float)(-56.0/15.0),(float)(32.0/9.0),0.f,0.f},
    {(float)(19372.0/6561.0),(float)(-25360.0/2187.0),(float)(64448.0/6561.0),(float)(-212.0/729.0),0.f},
    {(float)(9017.0/3168.0),(float)(-355.0/33.0),(float)(46732.0/5247.0),(float)(49.0/176.0),(float)(-5103.0/18656.0)}
};
__constant__ float c_cs[6] = {0.f, 0.2f, 0.3f, 0.8f, (float)(8.0/9.0), 1.f};
__constant__ float c_bb[6] = {(float)(35.0/384.0), 0.f, (float)(500.0/1113.0),
                              (float)(125.0/192.0), (float)(-2187.0/6784.0), (float)(11.0/84.0)};

// ---- f32x2 helpers ----
__device__ __forceinline__ void ffma2(unsigned long long& d, unsigned long long a, unsigned long long b) {
    asm("fma.rn.f32x2 %0, %1, %2, %0;" : "+l"(d) : "l"(a), "l"(b));
}
__device__ __forceinline__ unsigned long long pk(float a, float b) {
    unsigned long long r; asm("mov.b64 %0, {%1,%2};" : "=l"(r) : "f"(a), "f"(b)); return r;
}
__device__ __forceinline__ float2 upk(unsigned long long v) {
    float2 r; asm("mov.b64 {%0,%1}, %2;" : "=f"(r.x), "=f"(r.y) : "l"(v)); return r;
}

// ============================================================
// Transpose u[b][n][k] (256 x 32768) -> g_uT[(n*8+k)][b]
// ============================================================
__global__ void __launch_bounds__(256) transpose_u_kernel(const float* __restrict__ u) {
    __shared__ float tile[32][33];
    const int tx = threadIdx.x, ty = threadIdx.y;   // (32, 8)
    const int nk0 = blockIdx.x * 32;
    const int b0 = blockIdx.y * 32;
#pragma unroll
    for (int r = 0; r < 32; r += 8)
        tile[ty + r][tx] = u[(size_t)(b0 + ty + r) * (NT*NI) + nk0 + tx];
    __syncthreads();
#pragma unroll
    for (int r = 0; r < 32; r += 8)
        g_uT[(size_t)(nk0 + ty + r) * NB + b0 + tx] = tile[tx][ty + r];
}

// ============================================================
// Setup: exact affine map of one Dopri5 step, powers, transposes.
// ============================================================
__global__ void __launch_bounds__(1024) setup_kernel(const float* __restrict__ t,
                                                     const float* __restrict__ Am,
                                                     const float* __restrict__ Bm) {
    __shared__ float sA[NS*NS];      // A, later M
    __shared__ float sB[NS*NI];
    __shared__ float sP[6][NS*NS];
    __shared__ float sQ[6][NS*NI];
    __shared__ float sR[6][NS*NI];
    __shared__ float sT[NS*NS];
    __shared__ float sX[2*NS*NI];    // F0 | F1

    const int tid = threadIdx.x;
    const int i = tid >> 5, j = tid & 31;
    const float dt = t[1] - t[0];

    sA[tid] = Am[tid];
    if (j < NI) sB[i*NI + j] = Bm[i*NI + j];
    __syncthreads();

    for (int s = 0; s < 6; s++) {
        float tv = (i == j) ? 1.f : 0.f;
        float qv = 0.f, rv = 0.f;
        for (int js = 0; js < s; js++) {
            float a = dt * c_ac[s][js];
            tv += a * sP[js][tid];
            if (j < NI) {
                qv += a * sQ[js][i*NI + j];
                rv += a * sR[js][i*NI + j];
            }
        }
        __syncthreads();
        sT[tid] = tv;
        if (j < NI) { sX[i*NI + j] = qv; sX[NS*NI + i*NI + j] = rv; }
        __syncthreads();
        float pv = 0.f;
#pragma unroll
        for (int k = 0; k < NS; k++) pv += sA[i*NS + k] * sT[k*NS + j];
        sP[s][tid] = pv;
        if (j < NI) {
            float qa = 0.f, ra = 0.f;
#pragma unroll
            for (int k = 0; k < NS; k++) {
                qa += sA[i*NS + k] * sX[k*NI + j];
                ra += sA[i*NS + k] * sX[NS*NI + k*NI + j];
            }
            sQ[s][i*NI + j] = qa + sB[i*NI + j];
            sR[s][i*NI + j] = ra + c_cs[s] * sB[i*NI + j];
        }
        __syncthreads();
    }

    // M = I + dt Σ b_s P_s;  F0 = G0 - Gd, F1 = Gd
    float mv = (i == j) ? 1.f : 0.f;
    for (int s = 0; s < 6; s++) mv += dt * c_bb[s] * sP[s][tid];
    float f0v = 0.f, f1v = 0.f;
    if (j < NI) {
        float g0 = 0.f, gd = 0.f;
        for (int s = 0; s < 6; s++) {
            g0 += dt * c_bb[s] * sQ[s][i*NI + j];
            gd += dt * c_bb[s] * sR[s][i*NI + j];
        }
        f0v = g0 - gd; f1v = gd;
    }
    __syncthreads();
    sA[tid] = mv;                         // sA = M
    g_GTC2[j*NS + i] = make_float2(mv, mv);
    if (j < NI) {
        sX[i*NI + j] = f0v; sX[NS*NI + i*NI + j] = f1v;
        g_GTC2[(NS + j)*NS + i] = make_float2(f0v, f0v);
        g_GTC2[(NS + NI + j)*NS + i] = make_float2(f1v, f1v);
    }
    __syncthreads();

    // M2
    float m2 = 0.f;
#pragma unroll
    for (int k = 0; k < NS; k++) m2 += sA[i*NS + k] * sA[k*NS + j];
    __syncthreads();
    sT[tid] = m2;
    __syncthreads();
    // M3
    float m3 = 0.f;
#pragma unroll
    for (int k = 0; k < NS; k++) m3 += sT[i*NS + k] * sA[k*NS + j];
    sP[0][tid] = m3;
    __syncthreads();

    // Quad-step input maps: H0=M3F0, H1=M3F1+M2F0, H2=M2F1+MF0, H3=MF1+F0, H4=F1
    if (j < NI) {
        float h0 = 0.f, h1 = 0.f, h2 = 0.f, h3 = 0.f;
#pragma unroll
        for (int k = 0; k < NS; k++) {
            float fk0 = sX[k*NI + j], fk1 = sX[NS*NI + k*NI + j];
            h0 += sP[0][i*NS + k] * fk0;
            h1 += sP[0][i*NS + k] * fk1 + sT[i*NS + k] * fk0;
            h2 += sT[i*NS + k] * fk1 + sA[i*NS + k] * fk0;
            h3 += sA[i*NS + k] * fk1;
        }
        h3 += sX[i*NI + j];
        g_GTA[(NS + 0*NI + j)*NS + i] = h0;
        g_GTA[(NS + 1*NI + j)*NS + i] = h1;
        g_GTA[(NS + 2*NI + j)*NS + i] = h2;
        g_GTA[(NS + 3*NI + j)*NS + i] = h3;
        g_GTA[(NS + 4*NI + j)*NS + i] = sX[NS*NI + i*NI + j];
    }
    // M4
    float m4 = 0.f;
#pragma unroll
    for (int k = 0; k < NS; k++) m4 += sT[i*NS + k] * sT[k*NS + j];
    sP[1][tid] = m4;
    g_GTA[j*NS + i] = m4;
    __syncthreads();
    // M8
    float m8 = 0.f;
#pragma unroll
    for (int k = 0; k < NS; k++) m8 += sP[1][i*NS + k] * sP[1][k*NS + j];
    sP[2][tid] = m8;
    __syncthreads();
    // M16
    float m16 = 0.f;
#pragma unroll
    for (int k = 0; k < NS; k++) m16 += sP[2][i*NS + k] * sP[2][k*NS + j];
    sP[3][tid] = m16;
    g_M16T[j*NS + i] = m16;
    __syncthreads();
    // M32
    float m32 = 0.f;
#pragma unroll
    for (int k = 0; k < NS; k++) m32 += sP[3][i*NS + k] * sP[3][k*NS + j];
    g_M32T[j*NS + i] = m32;
}

// ============================================================
// Pass A: zero-start chunk partials, quad-step compressed.
// 32-thread blocks; thread = (batch lane, chunk). Coalesced u_T loads.
// ============================================================
__global__ void __launch_bounds__(32) passA_kernel() {
    __shared__ float sG[NAUGA*NS];
    __shared__ float sz[NAUGA*32];
    const int lane = threadIdx.x;
    const int c = blockIdx.x >> 3;
    const int b = ((blockIdx.x & 7) << 5) + lane;

    for (int k = lane; k < NAUGA*NS; k += 32) sG[k] = g_GTA[k];
#pragma unroll
    for (int ii = 0; ii < NS; ii++) sz[ii*32 + lane] = 0.f;

    const int n0 = c * CS;
    const int nq = (c == NCH - 1) ? 4 : 8;
#pragma unroll
    for (int k = 0; k < NI; k++)
        sz[(NS+k)*32 + lane] = g_uT[((size_t)n0*NI + k)*NB + b];
    __syncwarp();
    float* __restrict__ pout = &g_p[(size_t)(b*NCH + c) * 2 * NS];

#pragma unroll 1
    for (int q = 0; q < nq; q++) {
        const int n = n0 + q*4;
        float u4[NI];
#pragma unroll
        for (int p = 1; p <= 4; p++) {
            const int base = NS + 8*p;
#pragma unroll
            for (int k = 0; k < NI; k++) {
                float v = g_uT[((size_t)(n+p)*NI + k)*NB + b];
                sz[(base+k)*32 + lane] = v;
                if (p == 4) u4[k] = v;
            }
        }
        float acc[NS];
#pragma unroll
        for (int ii = 0; ii < NS; ii++) acc[ii] = 0.f;
#pragma unroll 2
        for (int jj = 0; jj < NAUGA; jj++) {
            const float zj = sz[jj*32 + lane];
            const float4* g4 = (const float4*)&sG[jj*NS];
#pragma unroll
            for (int qq = 0; qq < 8; qq++) {
                float4 w = g4[qq];
                acc[4*qq+0] = fmaf(w.x, zj, acc[4*qq+0]);
                acc[4*qq+1] = fmaf(w.y, zj, acc[4*qq+1]);
                acc[4*qq+2] = fmaf(w.z, zj, acc[4*qq+2]);
                acc[4*qq+3] = fmaf(w.w, zj, acc[4*qq+3]);
            }
        }
#pragma unroll
        for (int ii = 0; ii < NS; ii++) sz[ii*32 + lane] = acc[ii];
#pragma unroll
        for (int k = 0; k < NI; k++) sz[(NS+k)*32 + lane] = u4[k];
        if ((q & 3) == 3) {
            float4* po = (float4*)&pout[(q >> 2) * NS];
#pragma unroll
            for (int w2 = 0; w2 < 8; w2++)
                po[w2] = make_float4(acc[4*w2], acc[4*w2+1], acc[4*w2+2], acc[4*w2+3]);
        }
    }
}

// ============================================================
// Pass B: sequential chunk-boundary scan (warp per batch, shfl matvec, M^32)
// ============================================================
__global__ void __launch_bounds__(32) passB_kernel(const float* __restrict__ x0) {
    __shared__ float sMT[NS*NS];
    const int lane = threadIdx.x;
    const int b = blockIdx.x;
    for (int k = lane; k < NS*NS; k += 32) sMT[k] = g_M32T[k];
    __syncthreads();

    float x = x0[b*NS + lane];
    g_xstart[((size_t)b*NSUB + 0)*NS + lane] = x;
#pragma unroll 1
    for (int cc = 0; cc < NCH - 1; cc++) {
        float a0 = g_p[((size_t)(b*NCH + cc)*2 + 1)*NS + lane];
        float a1 = 0.f;
#pragma unroll
        for (int jv = 0; jv < NS; jv += 2) {
            a0 = fmaf(sMT[jv*NS + lane],     __shfl_sync(0xffffffffu, x, jv),   a0);
            a1 = fmaf(sMT[(jv+1)*NS + lane], __shfl_sync(0xffffffffu, x, jv+1), a1);
        }
        x = a0 + a1;
        g_xstart[((size_t)b*NSUB + 2*(cc+1))*NS + lane] = x;
    }
}

// ============================================================
// Pass B2: midpoint refinement. 256 blocks x 8 warps x 16 items;
// M16 loaded once per block (amortized).
// ============================================================
__global__ void __launch_bounds__(256) passB2_kernel() {
    __shared__ float s16[NS*NS];
    const int tid = threadIdx.x;
    const int lane = tid & 31, w = tid >> 5;
    for (int k = tid; k < NS*NS; k += 256) s16[k] = g_M16T[k];
    __syncthreads();

    const int gw0 = blockIdx.x * 128 + w * 16;
#pragma unroll 1
    for (int it = 0; it < 16; it++) {
        const int gw = gw0 + it;
        const int b = gw >> 7;
        const int c = gw & (NCH-1);
        float x = g_xstart[((size_t)b*NSUB + 2*c)*NS + lane];
        float a0 = g_p[((size_t)(b*NCH + c)*2 + 0)*NS + lane];
        float a1 = 0.f;
#pragma unroll
        for (int jv = 0; jv < NS; jv += 2) {
            a0 = fmaf(s16[jv*NS + lane],     __shfl_sync(0xffffffffu, x, jv),   a0);
            a1 = fmaf(s16[(jv+1)*NS + lane], __shfl_sync(0xffffffffu, x, jv+1), a1);
        }
        g_xstart[((size_t)b*NSUB + 2*c + 1)*NS + lane] = a0 + a1;
    }
}

// ============================================================
// Pass C: final trajectory + outputs. Thread = batch PAIR (b, b+64),
// f32x2 packed FMA against value-duplicated G. Coalesced staged xs flush.
// ============================================================
__global__ void __launch_bounds__(TPC) passC_kernel(const float* __restrict__ Cm,
                                                    const float* __restrict__ Dm,
                                                    float* __restrict__ xs,
                                                    float* __restrict__ ys) {
    __shared__ __align__(16) unsigned long long sG2[NAUGC*NS]; // dup pairs, [col][row]
    __shared__ unsigned long long szx[NS*TPC];                 // x state pairs, [row][thread]
    __shared__ float sxst[TPC*NS];                             // 64 rows x 32, chunk-swizzled staging
    __shared__ __align__(16) unsigned long long sC2[NO*NS];
    __shared__ __align__(16) unsigned long long sD2[NO*NI];
    const int tid = threadIdx.x;
    const int lane = tid & 31;
    const int sc = blockIdx.x >> 1;
    const int b0 = (blockIdx.x & 1) << 7;     // 0 or 128
    const int bA = b0 + tid;
    const int bB = b0 + tid + 64;

    {
        const unsigned long long* src = (const unsigned long long*)g_GTC2;
        for (int k = tid; k < NAUGC*NS; k += TPC) sG2[k] = src[k];
    }
    for (int k = tid; k < NO*NS; k += TPC) { float v = Cm[k]; sC2[k] = pk(v, v); }
    if (tid < NO*NI) { float v = Dm[tid]; sD2[tid] = pk(v, v); }
    __syncthreads();

    const int n0 = sc * SS;
    const int nsteps = (sc == NSUB - 1) ? (SS - 1) : SS;

    // init state pairs into szx
    {
        const float* xa = &g_xstart[((size_t)bA*NSUB + sc)*NS];
        const float* xb = &g_xstart[((size_t)bB*NSUB + sc)*NS];
#pragma unroll
        for (int i2 = 0; i2 < NS; i2++) szx[i2*TPC + tid] = pk(xa[i2], xb[i2]);
    }
    unsigned long long u0p[NI];
#pragma unroll
    for (int k = 0; k < NI; k++)
        u0p[k] = pk(g_uT[((size_t)n0*NI + k)*NB + bA],
                    g_uT[((size_t)n0*NI + k)*NB + bB]);

    if (sc == 0) {
        // emit t=0 sample (one-time; divergent stores acceptable)
        float* xsa = &xs[(size_t)bA*NT*NS];
        float* xsb = &xs[(size_t)bB*NT*NS];
        unsigned long long yv[NO];
#pragma unroll
        for (int o = 0; o < NO; o++) yv[o] = 0ull;
#pragma unroll
        for (int i2 = 0; i2 < NS; i2++) {
            float2 v = upk(szx[i2*TPC + tid]);
            xsa[i2] = v.x; xsb[i2] = v.y;
#pragma unroll
            for (int o = 0; o < NO; o++) ffma2(yv[o], sC2[o*NS + i2], szx[i2*TPC + tid]);
        }
#pragma unroll
        for (int o = 0; o < NO; o++) {
#pragma unroll
            for (int k = 0; k < NI; k++) ffma2(yv[o], sD2[o*NI + k], u0p[k]);
            float2 v = upk(yv[o]);
            ys[(size_t)bA*NT*NO + o] = v.x;
            ys[(size_t)bB*NT*NO + o] = v.y;
        }
    }

#pragma unroll 1
    for (int s2 = 0; s2 < nsteps; s2++) {
        const int n = n0 + s2;
        unsigned long long u1p[NI];
#pragma unroll
        for (int k = 0; k < NI; k++)
            u1p[k] = pk(g_uT[((size_t)(n+1)*NI + k)*NB + bA],
                        g_uT[((size_t)(n+1)*NI + k)*NB + bB]);

        unsigned long long nacc[NS];
#pragma unroll
        for (int i2 = 0; i2 < NS; i2++) nacc[i2] = 0ull;

        // x columns (z from shared, G dup-broadcast)
#pragma unroll 2
        for (int j = 0; j < NS; j++) {
            const unsigned long long zj = szx[j*TPC + tid];
            const ulonglong2* g2 = (const ulonglong2*)&sG2[j*NS];
#pragma unroll
            for (int q = 0; q < 16; q++) {
                ulonglong2 w = g2[q];
                ffma2(nacc[2*q],   w.x, zj);
                ffma2(nacc[2*q+1], w.y, zj);
            }
        }
        // u columns (z from registers)
#pragma unroll
        for (int k = 0; k < 2*NI; k++) {
            const unsigned long long zj = (k < NI) ? u0p[k] : u1p[k-NI];
            const ulonglong2* g2 = (const ulonglong2*)&sG2[(NS+k)*NS];
#pragma unroll
            for (int q = 0; q < 16; q++) {
                ulonglong2 w = g2[q];
                ffma2(nacc[2*q],   w.x, zj);
                ffma2(nacc[2*q+1], w.y, zj);
            }
        }
        // commit state
#pragma unroll
        for (int i2 = 0; i2 < NS; i2++) szx[i2*TPC + tid] = nacc[i2];
#pragma unroll
        for (int k = 0; k < NI; k++) u0p[k] = u1p[k];

        // y = C x + D u1
        unsigned long long yv[NO];
#pragma unroll
        for (int o = 0; o < NO; o++) {
            unsigned long long a = 0ull;
            const ulonglong2* c2 = (const ulonglong2*)&sC2[o*NS];
#pragma unroll
            for (int q = 0; q < 16; q++) {
                ulonglong2 w = c2[q];
                ffma2(a, w.x, nacc[2*q]);
                ffma2(a, w.y, nacc[2*q+1]);
            }
            const ulonglong2* d2 = (const ulonglong2*)&sD2[o*NI];
#pragma unroll
            for (int q = 0; q < 4; q++) {
                ulonglong2 w = d2[q];
                ffma2(a, w.x, u1p[2*q]);
                ffma2(a, w.y, u1p[2*q+1]);
            }
            yv[o] = a;
        }
        // ys stores (2x2 float4, divergent but small)
        {
            float2 t0=upk(yv[0]), t1=upk(yv[1]), t2=upk(yv[2]), t3=upk(yv[3]);
            float2 t4=upk(yv[4]), t5=upk(yv[5]), t6=upk(yv[6]), t7=upk(yv[7]);
            float4* ya = (float4*)&ys[((size_t)bA*NT + (n+1))*NO];
            ya[0] = make_float4(t0.x,t1.x,t2.x,t3.x);
            ya[1] = make_float4(t4.x,t5.x,t6.x,t7.x);
            float4* yb = (float4*)&ys[((size_t)bB*NT + (n+1))*NO];
            yb[0] = make_float4(t0.y,t1.y,t2.y,t3.y);
            yb[1] = make_float4(t4.y,t5.y,t6.y,t7.y);
        }

        // xs staged flush: phase 0 = .x half (batches b0+row), phase 1 = .y (b0+64+row)
        const int wr0 = (tid >> 5) << 5;      // warp's own 32 staging rows
#pragma unroll
        for (int ph = 0; ph < 2; ph++) {
            __syncwarp();
#pragma unroll
            for (int i2 = 0; i2 < NS; i2 += 2) {
                float2 v0 = upk(nacc[i2]), v1 = upk(nacc[i2+1]);
                float2 wv = ph ? make_float2(v0.y, v1.y) : make_float2(v0.x, v1.x);
                const int chunk = i2 >> 2;
                const int sw = ((chunk ^ (tid & 7)) << 2) + (i2 & 3);
                *(float2*)&sxst[tid*NS + sw] = wv;
            }
            __syncwarp();
            const int rbase = wr0 + (lane >> 3);
            const int cch = lane & 7;
            const int bofs = b0 + (ph ? 64 : 0);
#pragma unroll
            for (int rr = 0; rr < 32; rr += 4) {
                const int row = rbase + rr;
                float4 v = *(const float4*)&sxst[row*NS + ((cch ^ (row & 7)) << 2)];
                *(float4*)&xs[((size_t)(bofs + row)*NT + (n+1))*NS + (cch << 2)] = v;
            }
        }
    }
}

// ============================================================
extern "C" void kernel_launch(void* const* d_in, const int* in_sizes, int n_in,
                              void* d_out, int out_size) {
    const float* t  = (const float*)d_in[0];
    const float* u  = (const float*)d_in[1];
    const float* x0 = (const float*)d_in[2];
    const float* A  = (const float*)d_in[3];
    const float* B  = (const float*)d_in[4];
    const float* C  = (const float*)d_in[5];
    const float* D  = (const float*)d_in[6];
    float* xs = (float*)d_out;
    float* ys = xs + (size_t)NB * NT * NS;

    transpose_u_kernel<<<dim3(NT*NI/32, NB/32), dim3(32, 8)>>>(u);
    setup_kernel<<<1, 1024>>>(t, A, B);
    passA_kernel<<<NCH * 8, 32>>>();
    passB_kernel<<<NB, 32>>>(x0);
    passB2_kernel<<<256, 256>>>();
    passC_kernel<<<NSUB * 2, TPC>>>(C, D, xs, ys);
}

// round 6
// speedup vs baseline: 1.5796x; 1.0088x over previous
#include <cuda_runtime.h>

#define NS 32
#define NI 8
#define NO 8
#define NT 4096
#define NB 256
#define NCH 128
#define CS 32
#define NSUB 256
#define SS 16
#define NAUGA 72   // [x(32); u0..u4(40)]
#define NAUGC 48   // [x(32); u0(8); u1(8)]
#define TPC 64

// ---- persistent device scratch (module globals; no runtime allocation) ----
__device__ float g_uT[(size_t)NT*NI*NB];          // u transposed: [n][k][b]
__device__ __align__(16) float2 g_GTA2[NAUGA*NS]; // [M4 | H0..H4]^T dup-f32x2 (passA)
__device__ __align__(16) float2 g_GTC2[NAUGC*NS]; // [M | F0 | F1]^T dup-f32x2 (passC)
__device__ float g_M16T[NS*NS];
__device__ float g_M32T[NS*NS];
__device__ float g_PowT[7*NS*NS];                 // (M^32)^c transposed, c=1..7
__device__ float g_M256T[NS*NS];
__device__ float g_p[NB*NCH*2*NS];                // zero-start partials @ local steps 16,32
__device__ float g_pre[NB*16*8*NS];               // group-local prefixes (after c+1 chunks)
__device__ float g_gstart[NB*16*NS];              // group start states
__device__ float g_xstart[NB*NSUB*NS];            // 16-step subchunk start states

// ---- Dopri5 tableau in constant memory ----
__constant__ float c_ac[6][5] = {
    {0.f,0.f,0.f,0.f,0.f},
    {0.2f,0.f,0.f,0.f,0.f},
    {(float)(3.0/40.0),(float)(9.0/40.0),0.f,0.f,0.f},
    {(float)(44.0/45.0),(float)(-56.0/15.0),(float)(32.0/9.0),0.f,0.f},
    {(float)(19372.0/6561.0),(float)(-25360.0/2187.0),(float)(64448.0/6561.0),(float)(-212.0/729.0),0.f},
    {(float)(9017.0/3168.0),(float)(-355.0/33.0),(float)(46732.0/5247.0),(float)(49.0/176.0),(float)(-5103.0/18656.0)}
};
__constant__ float c_cs[6] = {0.f, 0.2f, 0.3f, 0.8f, (float)(8.0/9.0), 1.f};
__constant__ float c_bb[6] = {(float)(35.0/384.0), 0.f, (float)(500.0/1113.0),
                              (float)(125.0/192.0), (float)(-2187.0/6784.0), (float)(11.0/84.0)};

// ---- f32x2 helpers ----
__device__ __forceinline__ void ffma2(unsigned long long& d, unsigned long long a, unsigned long long b) {
    asm("fma.rn.f32x2 %0, %1, %2, %0;" : "+l"(d) : "l"(a), "l"(b));
}
__device__ __forceinline__ unsigned long long pk(float a, float b) {
    unsigned long long r; asm("mov.b64 %0, {%1,%2};" : "=l"(r) : "f"(a), "f"(b)); return r;
}
__device__ __forceinline__ float2 upk(unsigned long long v) {
    float2 r; asm("mov.b64 {%0,%1}, %2;" : "=f"(r.x), "=f"(r.y) : "l"(v)); return r;
}

// ============================================================
// Transpose u[b][n][k] (256 x 32768) -> g_uT[(n*8+k)][b]
// ============================================================
__global__ void __launch_bounds__(256) transpose_u_kernel(const float* __restrict__ u) {
    __shared__ float tile[32][33];
    const int tx = threadIdx.x, ty = threadIdx.y;   // (32, 8)
    const int nk0 = blockIdx.x * 32;
    const int b0 = blockIdx.y * 32;
#pragma unroll
    for (int r = 0; r < 32; r += 8)
        tile[ty + r][tx] = u[(size_t)(b0 + ty + r) * (NT*NI) + nk0 + tx];
    __syncthreads();
#pragma unroll
    for (int r = 0; r < 32; r += 8)
        g_uT[(size_t)(nk0 + ty + r) * NB + b0 + tx] = tile[tx][ty + r];
}

// ============================================================
// Setup: exact affine map of one Dopri5 step, powers, transposes.
// ============================================================
__global__ void __launch_bounds__(1024) setup_kernel(const float* __restrict__ t,
                                                     const float* __restrict__ Am,
                                                     const float* __restrict__ Bm) {
    __shared__ float sA[NS*NS];      // A, later M, later M^128 stash
    __shared__ float sB[NS*NI];
    __shared__ float sP[6][NS*NS];
    __shared__ float sQ[6][NS*NI];
    __shared__ float sR[6][NS*NI];
    __shared__ float sT[NS*NS];
    __shared__ float sX[2*NS*NI];    // F0 | F1

    const int tid = threadIdx.x;
    const int i = tid >> 5, j = tid & 31;
    const float dt = t[1] - t[0];

    sA[tid] = Am[tid];
    if (j < NI) sB[i*NI + j] = Bm[i*NI + j];
    __syncthreads();

    for (int s = 0; s < 6; s++) {
        float tv = (i == j) ? 1.f : 0.f;
        float qv = 0.f, rv = 0.f;
        for (int js = 0; js < s; js++) {
            float a = dt * c_ac[s][js];
            tv += a * sP[js][tid];
            if (j < NI) {
                qv += a * sQ[js][i*NI + j];
                rv += a * sR[js][i*NI + j];
            }
        }
        __syncthreads();
        sT[tid] = tv;
        if (j < NI) { sX[i*NI + j] = qv; sX[NS*NI + i*NI + j] = rv; }
        __syncthreads();
        float pv = 0.f;
#pragma unroll
        for (int k = 0; k < NS; k++) pv += sA[i*NS + k] * sT[k*NS + j];
        sP[s][tid] = pv;
        if (j < NI) {
            float qa = 0.f, ra = 0.f;
#pragma unroll
            for (int k = 0; k < NS; k++) {
                qa += sA[i*NS + k] * sX[k*NI + j];
                ra += sA[i*NS + k] * sX[NS*NI + k*NI + j];
            }
            sQ[s][i*NI + j] = qa + sB[i*NI + j];
            sR[s][i*NI + j] = ra + c_cs[s] * sB[i*NI + j];
        }
        __syncthreads();
    }

    // M = I + dt Σ b_s P_s;  F0 = G0 - Gd, F1 = Gd
    float mv = (i == j) ? 1.f : 0.f;
    for (int s = 0; s < 6; s++) mv += dt * c_bb[s] * sP[s][tid];
    float f0v = 0.f, f1v = 0.f;
    if (j < NI) {
        float g0 = 0.f, gd = 0.f;
        for (int s = 0; s < 6; s++) {
            g0 += dt * c_bb[s] * sQ[s][i*NI + j];
            gd += dt * c_bb[s] * sR[s][i*NI + j];
        }
        f0v = g0 - gd; f1v = gd;
    }
    __syncthreads();
    sA[tid] = mv;                         // sA = M
    g_GTC2[j*NS + i] = make_float2(mv, mv);
    if (j < NI) {
        sX[i*NI + j] = f0v; sX[NS*NI + i*NI + j] = f1v;
        g_GTC2[(NS + j)*NS + i] = make_float2(f0v, f0v);
        g_GTC2[(NS + NI + j)*NS + i] = make_float2(f1v, f1v);
    }
    __syncthreads();

    // M2
    float m2 = 0.f;
#pragma unroll
    for (int k = 0; k < NS; k++) m2 += sA[i*NS + k] * sA[k*NS + j];
    __syncthreads();
    sT[tid] = m2;
    __syncthreads();
    // M3
    float m3 = 0.f;
#pragma unroll
    for (int k = 0; k < NS; k++) m3 += sT[i*NS + k] * sA[k*NS + j];
    sP[0][tid] = m3;
    __syncthreads();

    // Quad-step input maps: H0=M3F0, H1=M3F1+M2F0, H2=M2F1+MF0, H3=MF1+F0, H4=F1
    if (j < NI) {
        float h0 = 0.f, h1 = 0.f, h2 = 0.f, h3 = 0.f;
#pragma unroll
        for (int k = 0; k < NS; k++) {
            float fk0 = sX[k*NI + j], fk1 = sX[NS*NI + k*NI + j];
            h0 += sP[0][i*NS + k] * fk0;
            h1 += sP[0][i*NS + k] * fk1 + sT[i*NS + k] * fk0;
            h2 += sT[i*NS + k] * fk1 + sA[i*NS + k] * fk0;
            h3 += sA[i*NS + k] * fk1;
        }
        h3 += sX[i*NI + j];
        g_GTA2[(NS + 0*NI + j)*NS + i] = make_float2(h0, h0);
        g_GTA2[(NS + 1*NI + j)*NS + i] = make_float2(h1, h1);
        g_GTA2[(NS + 2*NI + j)*NS + i] = make_float2(h2, h2);
        g_GTA2[(NS + 3*NI + j)*NS + i] = make_float2(h3, h3);
        float f1d = sX[NS*NI + i*NI + j];
        g_GTA2[(NS + 4*NI + j)*NS + i] = make_float2(f1d, f1d);
    }
    // M4
    float m4 = 0.f;
#pragma unroll
    for (int k = 0; k < NS; k++) m4 += sT[i*NS + k] * sT[k*NS + j];
    sP[1][tid] = m4;
    g_GTA2[j*NS + i] = make_float2(m4, m4);
    __syncthreads();
    // M8
    float m8 = 0.f;
#pragma unroll
    for (int k = 0; k < NS; k++) m8 += sP[1][i*NS + k] * sP[1][k*NS + j];
    sP[2][tid] = m8;
    __syncthreads();
    // M16
    float m16 = 0.f;
#pragma unroll
    for (int k = 0; k < NS; k++) m16 += sP[2][i*NS + k] * sP[2][k*NS + j];
    sP[3][tid] = m16;
    g_M16T[j*NS + i] = m16;
    __syncthreads();
    // M32 -> sP[4]; PowT[0]
    float m32 = 0.f;
#pragma unroll
    for (int k = 0; k < NS; k++) m32 += sP[3][i*NS + k] * sP[3][k*NS + j];
    sP[4][tid] = m32;
    g_M32T[j*NS + i] = m32;
    g_PowT[0*NS*NS + j*NS + i] = m32;
    __syncthreads();
    // c=2: M64 = M32*M32 -> sP[5]
    float cv = 0.f;
#pragma unroll
    for (int k = 0; k < NS; k++) cv += sP[4][i*NS + k] * sP[4][k*NS + j];
    sP[5][tid] = cv; g_PowT[1*NS*NS + j*NS + i] = cv;
    __syncthreads();
    // c=3: M96 = M64*M32 -> sT
    cv = 0.f;
#pragma unroll
    for (int k = 0; k < NS; k++) cv += sP[5][i*NS + k] * sP[4][k*NS + j];
    __syncthreads();
    sT[tid] = cv; g_PowT[2*NS*NS + j*NS + i] = cv;
    __syncthreads();
    // c=4: M128 = M96*M32 -> sP[5] and stash in sA
    cv = 0.f;
#pragma unroll
    for (int k = 0; k < NS; k++) cv += sT[i*NS + k] * sP[4][k*NS + j];
    __syncthreads();
    sP[5][tid] = cv; sA[tid] = cv; g_PowT[3*NS*NS + j*NS + i] = cv;
    __syncthreads();
    // c=5: M160 -> sT
    cv = 0.f;
#pragma unroll
    for (int k = 0; k < NS; k++) cv += sP[5][i*NS + k] * sP[4][k*NS + j];
    __syncthreads();
    sT[tid] = cv; g_PowT[4*NS*NS + j*NS + i] = cv;
    __syncthreads();
    // c=6: M192 -> sP[5]
    cv = 0.f;
#pragma unroll
    for (int k = 0; k < NS; k++) cv += sT[i*NS + k] * sP[4][k*NS + j];
    __syncthreads();
    sP[5][tid] = cv; g_PowT[5*NS*NS + j*NS + i] = cv;
    __syncthreads();
    // c=7: M224 (no shared write needed)
    cv = 0.f;
#pragma unroll
    for (int k = 0; k < NS; k++) cv += sP[5][i*NS + k] * sP[4][k*NS + j];
    g_PowT[6*NS*NS + j*NS + i] = cv;
    // M256 = M128*M128 (sA stash)
    cv = 0.f;
#pragma unroll
    for (int k = 0; k < NS; k++) cv += sA[i*NS + k] * sA[k*NS + j];
    g_M256T[j*NS + i] = cv;
}

// ============================================================
// Pass A: zero-start chunk partials, quad-step compressed, f32x2 batch pairs.
// 512 blocks x 32 threads; thread = batch pair (bA, bA+128) for one chunk.
// ============================================================
__global__ void __launch_bounds__(32) passA_kernel() {
    __shared__ __align__(16) unsigned long long sG2[NAUGA*NS];
    __shared__ unsigned long long sz[NAUGA*32];
    const int lane = threadIdx.x;
    const int c = blockIdx.x >> 2;
    const int bA = ((blockIdx.x & 3) << 5) + lane;
    const int bB = bA + 128;

    {
        const unsigned long long* src = (const unsigned long long*)g_GTA2;
        for (int k = lane; k < NAUGA*NS; k += 32) sG2[k] = src[k];
    }
#pragma unroll
    for (int ii = 0; ii < NS; ii++) sz[ii*32 + lane] = 0ull;

    const int n0 = c * CS;
    const int nq = (c == NCH - 1) ? 4 : 8;
#pragma unroll
    for (int k = 0; k < NI; k++)
        sz[(NS+k)*32 + lane] = pk(g_uT[((size_t)n0*NI + k)*NB + bA],
                                  g_uT[((size_t)n0*NI + k)*NB + bB]);
    __syncwarp();

#pragma unroll 1
    for (int q = 0; q < nq; q++) {
        const int n = n0 + q*4;
        unsigned long long u4[NI];
#pragma unroll
        for (int p = 1; p <= 4; p++) {
            const int base = NS + 8*p;
#pragma unroll
            for (int k = 0; k < NI; k++) {
                unsigned long long v = pk(g_uT[((size_t)(n+p)*NI + k)*NB + bA],
                                          g_uT[((size_t)(n+p)*NI + k)*NB + bB]);
                sz[(base+k)*32 + lane] = v;
                if (p == 4) u4[k] = v;
            }
        }
        unsigned long long acc[NS];
#pragma unroll
        for (int ii = 0; ii < NS; ii++) acc[ii] = 0ull;
#pragma unroll 2
        for (int jj = 0; jj < NAUGA; jj++) {
            const unsigned long long zj = sz[jj*32 + lane];
            const ulonglong2* g2 = (const ulonglong2*)&sG2[jj*NS];
#pragma unroll
            for (int qq = 0; qq < 16; qq++) {
                ulonglong2 w = g2[qq];
                ffma2(acc[2*qq],   w.x, zj);
                ffma2(acc[2*qq+1], w.y, zj);
            }
        }
#pragma unroll
        for (int ii = 0; ii < NS; ii++) sz[ii*32 + lane] = acc[ii];
#pragma unroll
        for (int k = 0; k < NI; k++) sz[(NS+k)*32 + lane] = u4[k];
        if ((q & 3) == 3) {
            float4* poA = (float4*)&g_p[((size_t)(bA*NCH + c)*2 + (q>>2))*NS];
            float4* poB = (float4*)&g_p[((size_t)(bB*NCH + c)*2 + (q>>2))*NS];
#pragma unroll
            for (int w2 = 0; w2 < 8; w2++) {
                float2 v0 = upk(acc[4*w2]),   v1 = upk(acc[4*w2+1]);
                float2 v2 = upk(acc[4*w2+2]), v3 = upk(acc[4*w2+3]);
                poA[w2] = make_float4(v0.x, v1.x, v2.x, v3.x);
                poB[w2] = make_float4(v0.y, v1.y, v2.y, v3.y);
            }
        }
    }
}

// ============================================================
// Pass B1: group-local prefix chains (parallel, 4096 warps).
// warp = (batch, group of 8 chunks); p values register-prefetched.
// ============================================================
__global__ void __launch_bounds__(128) passB1_kernel() {
    __shared__ float sMT[NS*NS];
    const int tid = threadIdx.x;
    const int lane = tid & 31, w = tid >> 5;
    const int gw = blockIdx.x * 4 + w;
    const int b = gw >> 4;
    const int g = gw & 15;
    for (int k = tid; k < NS*NS; k += 128) sMT[k] = g_M32T[k];
    __syncthreads();

    float p[8];
#pragma unroll
    for (int c2 = 0; c2 < 8; c2++)
        p[c2] = g_p[((size_t)(b*NCH + 8*g + c2)*2 + 1)*NS + lane];

    float s = p[0];
    g_pre[((size_t)(b*16 + g)*8 + 0)*NS + lane] = s;
#pragma unroll
    for (int c2 = 1; c2 < 8; c2++) {
        float a0 = p[c2], a1 = 0.f;
#pragma unroll
        for (int jv = 0; jv < NS; jv += 2) {
            a0 = fmaf(sMT[jv*NS + lane],     __shfl_sync(0xffffffffu, s, jv),   a0);
            a1 = fmaf(sMT[(jv+1)*NS + lane], __shfl_sync(0xffffffffu, s, jv+1), a1);
        }
        s = a0 + a1;
        g_pre[((size_t)(b*16 + g)*8 + c2)*NS + lane] = s;
    }
}

// ============================================================
// Pass B2: serial scan over 16 group boundaries (M^256), P preloaded.
// ============================================================
__global__ void __launch_bounds__(32) passB2_kernel(const float* __restrict__ x0) {
    __shared__ float sMT[NS*NS];
    const int lane = threadIdx.x;
    const int b = blockIdx.x;
    for (int k = lane; k < NS*NS; k += 32) sMT[k] = g_M256T[k];
    __syncthreads();

    float P[15];
#pragma unroll
    for (int g = 0; g < 15; g++)
        P[g] = g_pre[((size_t)(b*16 + g)*8 + 7)*NS + lane];

    float x = x0[b*NS + lane];
    g_gstart[((size_t)b*16 + 0)*NS + lane] = x;
#pragma unroll
    for (int g = 0; g < 15; g++) {
        float a0 = P[g], a1 = 0.f;
#pragma unroll
        for (int jv = 0; jv < NS; jv += 2) {
            a0 = fmaf(sMT[jv*NS + lane],     __shfl_sync(0xffffffffu, x, jv),   a0);
            a1 = fmaf(sMT[(jv+1)*NS + lane], __shfl_sync(0xffffffffu, x, jv+1), a1);
        }
        x = a0 + a1;
        g_gstart[((size_t)b*16 + g + 1)*NS + lane] = x;
    }
}

// ============================================================
// Pass B3: chunk starts via M32^c superposition + fused M16 midpoints.
// 256 blocks x 8 warps; warp c handles chunk (8g+c) for 16 batches.
// ============================================================
__global__ void __launch_bounds__(256) passB3_kernel() {
    __shared__ float sPow[8][NS*NS];  // [0]=M16T, [w]=M32^w T
    const int tid = threadIdx.x;
    const int lane = tid & 31, w = tid >> 5;
    const int g = blockIdx.x & 15;
    const int bb = blockIdx.x >> 4;
    for (int k = lane; k < NS*NS; k += 32)
        sPow[w][k] = (w == 0) ? g_M16T[k] : g_PowT[(w-1)*NS*NS + k];
    __syncthreads();

    const int chunk = 8*g + w;
#pragma unroll 1
    for (int it = 0; it < 16; it++) {
        const int b = bb*16 + it;
        float xg = g_gstart[((size_t)b*16 + g)*NS + lane];
        float xc;
        if (w == 0) {
            xc = xg;
        } else {
            float a0 = g_pre[((size_t)(b*16 + g)*8 + (w-1))*NS + lane];
            float a1 = 0.f;
#pragma unroll
            for (int jv = 0; jv < NS; jv += 2) {
                a0 = fmaf(sPow[w][jv*NS + lane],     __shfl_sync(0xffffffffu, xg, jv),   a0);
                a1 = fmaf(sPow[w][(jv+1)*NS + lane], __shfl_sync(0xffffffffu, xg, jv+1), a1);
            }
            xc = a0 + a1;
        }
        g_xstart[((size_t)b*NSUB + 2*chunk)*NS + lane] = xc;

        float m0 = g_p[((size_t)(b*NCH + chunk)*2 + 0)*NS + lane];
        float m1 = 0.f;
#pragma unroll
        for (int jv = 0; jv < NS; jv += 2) {
            m0 = fmaf(sPow[0][jv*NS + lane],     __shfl_sync(0xffffffffu, xc, jv),   m0);
            m1 = fmaf(sPow[0][(jv+1)*NS + lane], __shfl_sync(0xffffffffu, xc, jv+1), m1);
        }
        g_xstart[((size_t)b*NSUB + 2*chunk + 1)*NS + lane] = m0 + m1;
    }
}

// ============================================================
// Pass C: final trajectory + outputs. Thread = batch PAIR (b, b+64),
// f32x2 packed FMA; coalesced staged xs flush.
// ============================================================
__global__ void __launch_bounds__(TPC) passC_kernel(const float* __restrict__ Cm,
                                                    const float* __restrict__ Dm,
                                                    float* __restrict__ xs,
                                                    float* __restrict__ ys) {
    __shared__ __align__(16) unsigned long long sG2[NAUGC*NS];
    __shared__ unsigned long long szx[NS*TPC];
    __shared__ float sxst[TPC*NS];
    __shared__ __align__(16) unsigned long long sC2[NO*NS];
    __shared__ __align__(16) unsigned long long sD2[NO*NI];
    const int tid = threadIdx.x;
    const int lane = tid & 31;
    const int sc = blockIdx.x >> 1;
    const int b0 = (blockIdx.x & 1) << 7;
    const int bA = b0 + tid;
    const int bB = b0 + tid + 64;

    {
        const unsigned long long* src = (const unsigned long long*)g_GTC2;
        for (int k = tid; k < NAUGC*NS; k += TPC) sG2[k] = src[k];
    }
    for (int k = tid; k < NO*NS; k += TPC) { float v = Cm[k]; sC2[k] = pk(v, v); }
    if (tid < NO*NI) { float v = Dm[tid]; sD2[tid] = pk(v, v); }
    __syncthreads();

    const int n0 = sc * SS;
    const int nsteps = (sc == NSUB - 1) ? (SS - 1) : SS;

    {
        const float* xa = &g_xstart[((size_t)bA*NSUB + sc)*NS];
        const float* xb = &g_xstart[((size_t)bB*NSUB + sc)*NS];
#pragma unroll
        for (int i2 = 0; i2 < NS; i2++) szx[i2*TPC + tid] = pk(xa[i2], xb[i2]);
    }
    unsigned long long u0p[NI];
#pragma unroll
    for (int k = 0; k < NI; k++)
        u0p[k] = pk(g_uT[((size_t)n0*NI + k)*NB + bA],
                    g_uT[((size_t)n0*NI + k)*NB + bB]);

    if (sc == 0) {
        float* xsa = &xs[(size_t)bA*NT*NS];
        float* xsb = &xs[(size_t)bB*NT*NS];
        unsigned long long yv[NO];
#pragma unroll
        for (int o = 0; o < NO; o++) yv[o] = 0ull;
#pragma unroll
        for (int i2 = 0; i2 < NS; i2++) {
            float2 v = upk(szx[i2*TPC + tid]);
            xsa[i2] = v.x; xsb[i2] = v.y;
#pragma unroll
            for (int o = 0; o < NO; o++) ffma2(yv[o], sC2[o*NS + i2], szx[i2*TPC + tid]);
        }
#pragma unroll
        for (int o = 0; o < NO; o++) {
#pragma unroll
            for (int k = 0; k < NI; k++) ffma2(yv[o], sD2[o*NI + k], u0p[k]);
            float2 v = upk(yv[o]);
            ys[(size_t)bA*NT*NO + o] = v.x;
            ys[(size_t)bB*NT*NO + o] = v.y;
        }
    }

#pragma unroll 1
    for (int s2 = 0; s2 < nsteps; s2++) {
        const int n = n0 + s2;
        unsigned long long u1p[NI];
#pragma unroll
        for (int k = 0; k < NI; k++)
            u1p[k] = pk(g_uT[((size_t)(n+1)*NI + k)*NB + bA],
                        g_uT[((size_t)(n+1)*NI + k)*NB + bB]);

        unsigned long long nacc[NS];
#pragma unroll
        for (int i2 = 0; i2 < NS; i2++) nacc[i2] = 0ull;

#pragma unroll 2
        for (int j = 0; j < NS; j++) {
            const unsigned long long zj = szx[j*TPC + tid];
            const ulonglong2* g2 = (const ulonglong2*)&sG2[j*NS];
#pragma unroll
            for (int q = 0; q < 16; q++) {
                ulonglong2 w = g2[q];
                ffma2(nacc[2*q],   w.x, zj);
                ffma2(nacc[2*q+1], w.y, zj);
            }
        }
#pragma unroll
        for (int k = 0; k < 2*NI; k++) {
            const unsigned long long zj = (k < NI) ? u0p[k] : u1p[k-NI];
            const ulonglong2* g2 = (const ulonglong2*)&sG2[(NS+k)*NS];
#pragma unroll
            for (int q = 0; q < 16; q++) {
                ulonglong2 w = g2[q];
                ffma2(nacc[2*q],   w.x, zj);
                ffma2(nacc[2*q+1], w.y, zj);
            }
        }
#pragma unroll
        for (int i2 = 0; i2 < NS; i2++) szx[i2*TPC + tid] = nacc[i2];
#pragma unroll
        for (int k = 0; k < NI; k++) u0p[k] = u1p[k];

        unsigned long long yv[NO];
#pragma unroll
        for (int o = 0; o < NO; o++) {
            unsigned long long a = 0ull;
            const ulonglong2* c2 = (const ulonglong2*)&sC2[o*NS];
#pragma unroll
            for (int q = 0; q < 16; q++) {
                ulonglong2 w = c2[q];
                ffma2(a, w.x, nacc[2*q]);
                ffma2(a, w.y, nacc[2*q+1]);
            }
            const ulonglong2* d2 = (const ulonglong2*)&sD2[o*NI];
#pragma unroll
            for (int q = 0; q < 4; q++) {
                ulonglong2 w = d2[q];
                ffma2(a, w.x, u1p[2*q]);
                ffma2(a, w.y, u1p[2*q+1]);
            }
            yv[o] = a;
        }
        {
            float2 t0=upk(yv[0]), t1=upk(yv[1]), t2=upk(yv[2]), t3=upk(yv[3]);
            float2 t4=upk(yv[4]), t5=upk(yv[5]), t6=upk(yv[6]), t7=upk(yv[7]);
            float4* ya = (float4*)&ys[((size_t)bA*NT + (n+1))*NO];
            ya[0] = make_float4(t0.x,t1.x,t2.x,t3.x);
            ya[1] = make_float4(t4.x,t5.x,t6.x,t7.x);
            float4* yb = (float4*)&ys[((size_t)bB*NT + (n+1))*NO];
            yb[0] = make_float4(t0.y,t1.y,t2.y,t3.y);
            yb[1] = make_float4(t4.y,t5.y,t6.y,t7.y);
        }

        const int wr0 = (tid >> 5) << 5;
#pragma unroll
        for (int ph = 0; ph < 2; ph++) {
            __syncwarp();
#pragma unroll
            for (int i2 = 0; i2 < NS; i2 += 2) {
                float2 v0 = upk(nacc[i2]), v1 = upk(nacc[i2+1]);
                float2 wv = ph ? make_float2(v0.y, v1.y) : make_float2(v0.x, v1.x);
                const int chunk = i2 >> 2;
                const int sw = ((chunk ^ (tid & 7)) << 2) + (i2 & 3);
                *(float2*)&sxst[tid*NS + sw] = wv;
            }
            __syncwarp();
            const int rbase = wr0 + (lane >> 3);
            const int cch = lane & 7;
            const int bofs = b0 + (ph ? 64 : 0);
#pragma unroll
            for (int rr = 0; rr < 32; rr += 4) {
                const int row = rbase + rr;
                float4 v = *(const float4*)&sxst[row*NS + ((cch ^ (row & 7)) << 2)];
                *(float4*)&xs[((size_t)(bofs + row)*NT + (n+1))*NS + (cch << 2)] = v;
            }
        }
    }
}

// ============================================================
extern "C" void kernel_launch(void* const* d_in, const int* in_sizes, int n_in,
                              void* d_out, int out_size) {
    const float* t  = (const float*)d_in[0];
    const float* u  = (const float*)d_in[1];
    const float* x0 = (const float*)d_in[2];
    const float* A  = (const float*)d_in[3];
    const float* B  = (const float*)d_in[4];
    const float* C  = (const float*)d_in[5];
    const float* D  = (const float*)d_in[6];
    float* xs = (float*)d_out;
    float* ys = xs + (size_t)NB * NT * NS;

    transpose_u_kernel<<<dim3(NT*NI/32, NB/32), dim3(32, 8)>>>(u);
    setup_kernel<<<1, 1024>>>(t, A, B);
    passA_kernel<<<NCH * 4, 32>>>();
    passB1_kernel<<<1024, 128>>>();
    passB2_kernel<<<NB, 32>>>(x0);
    passB3_kernel<<<256, 256>>>();
    passC_kernel<<<NSUB * 2, TPC>>>(C, D, xs, ys);
}